// round 4
// baseline (speedup 1.0000x reference)
#include <cuda_runtime.h>
#include <cstdint>

// CapsuleLayer: conv(stride2,3x3) via mma.sync tf32, 3x dynamic routing, transpose.
// x: [8,8,32,64,64] fp32   W: [512,32,3,3]   bias: [512]
// out: [8,8,64,32,32] (N,T1,Z1,H1,W1) fp32

#define DEVINL __device__ __forceinline__

DEVINL uint32_t smem_u32(const void* p) {
    uint32_t a;
    asm("{ .reg .u64 t; cvta.to.shared.u64 t, %1; cvt.u32.u64 %0, t; }" : "=r"(a) : "l"(p));
    return a;
}
DEVINL void cp16(uint32_t dst, const void* src) {
    asm volatile("cp.async.cg.shared.global [%0], [%1], 16;" ::"r"(dst), "l"(src) : "memory");
}
// K-permutation: within each 16-k half, k -> (k%4)*4 + (k%16)/4  (fragment vectorization)
DEVINL int kperm(int k) { return ((k & 3) << 2) | ((k & 15) >> 2) | (k & 16); }

// ---------------------------------------------------------------------------
__device__ __align__(128) float g_xt[64 * 66 * 66 * 32];        // NHWC padded, tf32, k-permuted
__device__ __align__(128) float g_w2[9 * 512 * 32];             // [kpos][oc][ic-perm], tf32
__device__ __align__(128) float g_u2[8 * 32 * 32 * 8 * 8 * 64]; // [n][h][w][t0][t1][z]
__device__ __align__(128) float g_b [8 * 8 * 32 * 32 * 8];      // [n][t0][h][w][t1]
__device__ __align__(128) float g_r [8 * 8 * 32 * 32 * 8];
__device__ __align__(128) float g_vs[8 * 32 * 32 * 512];        // [n][h][w][t1*64+z]

// ---------------------------------------------------------------------------
// 1) x -> g_xt  (NCHW -> padded NHWC, tf32 rounding, ic permuted)
// ---------------------------------------------------------------------------
__global__ __launch_bounds__(256) void xt_kernel(const float* __restrict__ x) {
    __shared__ float s[64 * 33];
    const int b = blockIdx.y, h0 = blockIdx.x;
    const int t = threadIdx.x;
    const int lane = t & 31, icg = t >> 5;
    const float* xp = x + ((size_t)(b * 32) * 64 + h0) * 64;
#pragma unroll
    for (int i = 0; i < 4; i++) {
        int ic = icg + 8 * i;
        s[lane * 33 + ic]        = xp[(size_t)ic * 4096 + lane];
        s[(lane + 32) * 33 + ic] = xp[(size_t)ic * 4096 + lane + 32];
    }
    __syncthreads();
    uint32_t* dst = (uint32_t*)(g_xt + (((size_t)b * 66 + h0 + 1) * 66 + 1) * 32);
#pragma unroll
    for (int i = 0; i < 8; i++) {
        int idx = t + 256 * i;
        int w0 = idx >> 5, ic = idx & 31;
        uint32_t u;
        asm("cvt.rna.tf32.f32 %0, %1;" : "=r"(u) : "f"(s[w0 * 33 + ic]));
        dst[w0 * 32 + kperm(ic)] = u;
    }
}

// ---------------------------------------------------------------------------
// 2) W -> g_w2 [kpos][oc][ic-perm] tf32
// ---------------------------------------------------------------------------
__global__ void w2_kernel(const float* __restrict__ W) {
    int idx = blockIdx.x * 256 + threadIdx.x;   // oc*288 + ic*9 + kp
    if (idx >= 512 * 288) return;
    int oc = idx / 288, r = idx % 288, ic = r / 9, kp = r % 9;
    uint32_t u;
    asm("cvt.rna.tf32.f32 %0, %1;" : "=r"(u) : "f"(W[idx]));
    ((uint32_t*)g_w2)[((size_t)kp * 512 + oc) * 32 + kperm(ic)] = u;
}

// ---------------------------------------------------------------------------
// 3) conv via mma.sync tf32: D[oc=128][px=128], K = 9*32, double-buffered.
//    Fragments loaded as LDS.128 thanks to k-permuted tiles.
// ---------------------------------------------------------------------------
#define TSTRIDE 36
#define TILE_F  (128 * TSTRIDE)

__global__ __launch_bounds__(256, 2) void conv_mma_kernel(const float* __restrict__ bias) {
    extern __shared__ float dsm[];
    const uint32_t sbase = smem_u32(dsm);
    const uint32_t offA[2] = {0u, 2u * TILE_F * 4u};      // bytes
    const uint32_t offB[2] = {TILE_F * 4u, 3u * TILE_F * 4u};

    const int tid = threadIdx.x;
    const int wid = tid >> 5, lane = tid & 31;
    const int gid = lane >> 2, tig = lane & 3;

    const int pt = blockIdx.x;
    const int m  = blockIdx.y;
    const int b  = blockIdx.z;
    const int h0 = pt * 4;

    const int m0 = (wid & 1) * 64;
    const int n0 = (wid >> 1) * 32;

    float acc[4][4][4];
#pragma unroll
    for (int mi = 0; mi < 4; mi++)
#pragma unroll
        for (int ni = 0; ni < 4; ni++)
#pragma unroll
            for (int j = 0; j < 4; j++) acc[mi][ni][j] = 0.f;

    auto issue = [&](int s, int buf) {
        const int kh = s / 3, kw = s % 3;
        const float4* Asrc = (const float4*)g_w2 + ((size_t)s * 512 + m * 128) * 8;
        const int ihb = 2 * h0 + kh;
#pragma unroll
        for (int i = 0; i < 4; i++) {
            int c = tid + 256 * i;
            int o = c >> 3, q = c & 7;
            cp16(sbase + offA[buf] + (o * TSTRIDE + q * 4) * 4, Asrc + c);
            int hl = o >> 5, wl = o & 31;
            const float4* src =
                (const float4*)g_xt + (((size_t)b * 66 + ihb + 2 * hl) * 66 + 2 * wl + kw) * 8 + q;
            cp16(sbase + offB[buf] + (o * TSTRIDE + q * 4) * 4, src);
        }
        asm volatile("cp.async.commit_group;");
    };

    issue(0, 0);

    for (int s = 0; s < 9; s++) {
        if (s < 8) {
            issue(s + 1, (s + 1) & 1);
            asm volatile("cp.async.wait_group 1;" ::: "memory");
        } else {
            asm volatile("cp.async.wait_group 0;" ::: "memory");
        }
        __syncthreads();

        const float* sA = dsm + (offA[s & 1] >> 2);
        const float* sB = dsm + (offB[s & 1] >> 2);

#pragma unroll
        for (int h = 0; h < 2; h++) {
            uint4 bfr[4];
#pragma unroll
            for (int ni = 0; ni < 4; ni++) {
                int cn = n0 + ni * 8 + gid;
                bfr[ni] = *(const uint4*)(sB + cn * TSTRIDE + h * 16 + tig * 4);
            }
#pragma unroll
            for (int mp = 0; mp < 2; mp++) {
                uint4 af[2][2];
#pragma unroll
                for (int m2 = 0; m2 < 2; m2++) {
                    int r = m0 + (mp * 2 + m2) * 16 + gid;
                    af[m2][0] = *(const uint4*)(sA + r * TSTRIDE + h * 16 + tig * 4);
                    af[m2][1] = *(const uint4*)(sA + (r + 8) * TSTRIDE + h * 16 + tig * 4);
                }
#pragma unroll
                for (int sub = 0; sub < 2; sub++) {
#pragma unroll
                    for (int m2 = 0; m2 < 2; m2++) {
                        const uint32_t* a0 = (const uint32_t*)&af[m2][0];
                        const uint32_t* a1 = (const uint32_t*)&af[m2][1];
                        float* ac = acc[mp * 2 + m2][0];
#pragma unroll
                        for (int ni = 0; ni < 4; ni++) {
                            const uint32_t* bb = (const uint32_t*)&bfr[ni];
                            float* A = acc[mp * 2 + m2][ni];
                            asm volatile(
                                "mma.sync.aligned.m16n8k8.row.col.f32.tf32.tf32.f32 "
                                "{%0,%1,%2,%3}, {%4,%5,%6,%7}, {%8,%9}, {%0,%1,%2,%3};"
                                : "+f"(A[0]), "+f"(A[1]), "+f"(A[2]), "+f"(A[3])
                                : "r"(a0[2 * sub]), "r"(a1[2 * sub]),
                                  "r"(a0[2 * sub + 1]), "r"(a1[2 * sub + 1]),
                                  "r"(bb[2 * sub]), "r"(bb[2 * sub + 1]));
                        }
                        (void)ac;
                    }
                }
            }
        }
        __syncthreads();
    }

    // Epilogue: regs -> stage[px][oc] (+bias) -> g_u2
    float* stage = dsm;
#pragma unroll
    for (int mi = 0; mi < 4; mi++) {
        int r = m0 + mi * 16 + gid;
        float bi0 = bias[m * 128 + r];
        float bi1 = bias[m * 128 + r + 8];
#pragma unroll
        for (int ni = 0; ni < 4; ni++) {
            int cn = n0 + ni * 8 + 2 * tig;
            stage[cn * 132 + r]           = acc[mi][ni][0] + bi0;
            stage[(cn + 1) * 132 + r]     = acc[mi][ni][1] + bi0;
            stage[cn * 132 + r + 8]       = acc[mi][ni][2] + bi1;
            stage[(cn + 1) * 132 + r + 8] = acc[mi][ni][3] + bi1;
        }
    }
    __syncthreads();

    const int n = b >> 3, t0 = b & 7;
#pragma unroll
    for (int k = 0; k < 16; k++) {
        int idx = tid + 256 * k;
        int p = idx >> 5, q = idx & 31;
        int h = h0 + (p >> 5), w = p & 31;
        float4 v = *(const float4*)(stage + p * 132 + q * 4);
        size_t off = ((((size_t)(n * 32 + h) * 32 + w) * 8 + t0) * 512) + m * 128 + q * 4;
        *(float4*)(g_u2 + off) = v;
    }
}

// ---------------------------------------------------------------------------
// 4) Routing iteration: u slice held in registers (no smem staging).
// ---------------------------------------------------------------------------
template <int MODE>
__global__ __launch_bounds__(128) void route_kernel() {
    __shared__ float sr[64];

    const int pix = blockIdx.x;
    const int n = pix >> 10;
    const int hw = pix & 1023;
    const int tid = threadIdx.x;
    const int t1 = tid >> 4;
    const int z4 = tid & 15;

    if (MODE >= 1 && tid < 64) {
        int rt0 = tid >> 3, rt1 = tid & 7;
        sr[tid] = g_r[((n * 8 + rt0) * 1024 + hw) * 8 + rt1];
    }

    float4 u[8];
    const float4* up = (const float4*)g_u2 + (size_t)pix * 1024 + t1 * 16 + z4;
#pragma unroll
    for (int t0 = 0; t0 < 8; t0++) u[t0] = up[t0 * 128];

    if (MODE >= 1) __syncthreads();

    float4 p = make_float4(0.f, 0.f, 0.f, 0.f);
#pragma unroll
    for (int t0 = 0; t0 < 8; t0++) {
        float r = (MODE == 0) ? 0.125f : sr[t0 * 8 + t1];
        p.x += r * u[t0].x; p.y += r * u[t0].y; p.z += r * u[t0].z; p.w += r * u[t0].w;
    }
    float n2 = p.x * p.x + p.y * p.y + p.z * p.z + p.w * p.w;
#pragma unroll
    for (int mm = 1; mm < 16; mm <<= 1) n2 += __shfl_xor_sync(0xffffffffu, n2, mm);
    float s = n2 / (1.f + n2) * rsqrtf(n2 + 1e-9f);
    float4 v = make_float4(p.x * s, p.y * s, p.z * s, p.w * s);

    if (MODE == 2) {
        ((float4*)(g_vs + (size_t)pix * 512))[tid] = v;
    } else {
        float d[8];
#pragma unroll
        for (int t0 = 0; t0 < 8; t0++)
            d[t0] = u[t0].x * v.x + u[t0].y * v.y + u[t0].z * v.z + u[t0].w * v.w;
#pragma unroll
        for (int mm = 1; mm < 16; mm <<= 1) {
#pragma unroll
            for (int t0 = 0; t0 < 8; t0++)
                d[t0] += __shfl_xor_sync(0xffffffffu, d[t0], mm);
        }
        if ((tid & 15) == 0) {
#pragma unroll
            for (int t0 = 0; t0 < 8; t0++) {
                float* bp = &g_b[((n * 8 + t0) * 1024 + hw) * 8 + t1];
                if (MODE == 0) *bp = d[t0];
                else           *bp += d[t0];
            }
        }
    }
}

// ---------------------------------------------------------------------------
// 5) r = softmax_t1(maxpool3x3(b)).  grid (band=4, nt=64), 256 thr, h-banded.
// ---------------------------------------------------------------------------
__global__ __launch_bounds__(256) void pool_softmax_kernel() {
    __shared__ float sb[10 * 32 * 8];     // rows h_base..h_base+9
    const int band = blockIdx.x, nt = blockIdx.y;
    const int tid = threadIdx.x;
    const int h_base = band * 8 - 1;

    for (int i = tid; i < 640; i += 256) {     // 640 float4 = 10 rows * 64
        int lr = i >> 6, rem = i & 63;
        int gh = h_base + lr;
        float4 v;
        if (gh >= 0 && gh < 32)
            v = ((const float4*)(g_b + nt * 8192 + gh * 256))[rem];
        else
            v = make_float4(-3.4e38f, -3.4e38f, -3.4e38f, -3.4e38f);
        ((float4*)sb)[i] = v;
    }
    __syncthreads();

    const int hl = tid >> 5, w = tid & 31;    // hl 0..7 within band
    float m[8];
#pragma unroll
    for (int t = 0; t < 8; t++) m[t] = -3.4e38f;
#pragma unroll
    for (int dh = 0; dh < 3; dh++) {
        int lr = hl + dh;                     // local row (halo offset +1 built in)
#pragma unroll
        for (int dw = -1; dw <= 1; dw++) {
            int ww = w + dw;
            if (ww < 0 || ww > 31) continue;
            const float* pp = &sb[(lr * 32 + ww) * 8];
#pragma unroll
            for (int t = 0; t < 8; t++) m[t] = fmaxf(m[t], pp[t]);
        }
    }
    float mx = m[0];
#pragma unroll
    for (int t = 1; t < 8; t++) mx = fmaxf(mx, m[t]);
    float e[8], ssum = 0.f;
#pragma unroll
    for (int t = 0; t < 8; t++) { e[t] = expf(m[t] - mx); ssum += e[t]; }
    float inv = 1.f / ssum;
    float* dst = &g_r[nt * 8192 + ((band * 8 + hl) * 32 + w) * 8];
    *(float4*)(dst + 0) = make_float4(e[0] * inv, e[1] * inv, e[2] * inv, e[3] * inv);
    *(float4*)(dst + 4) = make_float4(e[4] * inv, e[5] * inv, e[6] * inv, e[7] * inv);
}

// ---------------------------------------------------------------------------
// 6) transpose g_vs [n][hw][tz] -> out [n][tz][hw]
// ---------------------------------------------------------------------------
__global__ __launch_bounds__(256) void transpose_kernel(float* __restrict__ out) {
    __shared__ float t[32][33];
    const int n = blockIdx.z;
    const int x0 = blockIdx.x * 32;
    const int y0 = blockIdx.y * 32;
    const int tx = threadIdx.x & 31;
    const int ty = threadIdx.x >> 5;
    const float* src = g_vs + (size_t)n * 1024 * 512;
    float* dst = out + (size_t)n * 512 * 1024;
#pragma unroll
    for (int i = 0; i < 4; i++) {
        int y = ty + i * 8;
        t[y][tx] = src[(y0 + y) * 512 + x0 + tx];
    }
    __syncthreads();
#pragma unroll
    for (int i = 0; i < 4; i++) {
        int y = ty + i * 8;
        dst[(x0 + y) * 1024 + y0 + tx] = t[tx][y];
    }
}

// ---------------------------------------------------------------------------
extern "C" void kernel_launch(void* const* d_in, const int* in_sizes, int n_in,
                              void* d_out, int out_size) {
    const float* x    = (const float*)d_in[0];
    const float* W    = (const float*)d_in[1];
    const float* bias = (const float*)d_in[2];
    float* out = (float*)d_out;

    static bool attr_done = false;
    if (!attr_done) {
        cudaFuncSetAttribute(conv_mma_kernel,
                             cudaFuncAttributeMaxDynamicSharedMemorySize, 4 * TILE_F * 4);
        attr_done = true;
    }

    xt_kernel<<<dim3(64, 64), 256>>>(x);
    w2_kernel<<<576, 256>>>(W);
    conv_mma_kernel<<<dim3(8, 4, 64), 256, 4 * TILE_F * 4>>>(bias);

    route_kernel<0><<<8192, 128>>>();
    pool_softmax_kernel<<<dim3(4, 64), 256>>>();
    route_kernel<1><<<8192, 128>>>();
    pool_softmax_kernel<<<dim3(4, 64), 256>>>();
    route_kernel<2><<<8192, 128>>>();

    dim3 tg(16, 32, 8);
    transpose_kernel<<<tg, 256>>>(out);
}

// round 7
// speedup vs baseline: 1.1630x; 1.1630x over previous
#include <cuda_runtime.h>
#include <cstdint>

// CapsuleLayer: conv(stride2,3x3) via mma.sync tf32, 3x dynamic routing, transpose.
// x: [8,8,32,64,64] fp32   W: [512,32,3,3]   bias: [512]
// out: [8,8,64,32,32] (N,T1,Z1,H1,W1) fp32

#define DEVINL __device__ __forceinline__

DEVINL uint32_t smem_u32(const void* p) {
    uint32_t a;
    asm("{ .reg .u64 t; cvta.to.shared.u64 t, %1; cvt.u32.u64 %0, t; }" : "=r"(a) : "l"(p));
    return a;
}
DEVINL void cp16(uint32_t dst, const void* src) {
    asm volatile("cp.async.cg.shared.global [%0], [%1], 16;" ::"r"(dst), "l"(src) : "memory");
}

// ---------------------------------------------------------------------------
__device__ __align__(128) float g_xt[64 * 66 * 66 * 32];        // NHWC padded, tf32
__device__ __align__(128) float g_w2[9 * 512 * 32];             // [kpos][oc][ic], tf32
__device__ __align__(128) float g_u2[8 * 32 * 32 * 8 * 8 * 64]; // [n][h][w][t0][t1][z]
__device__ __align__(128) float g_b [8 * 8 * 32 * 32 * 8];      // [n][t0][h][w][t1]
__device__ __align__(128) float g_r [8 * 8 * 32 * 32 * 8];
__device__ __align__(128) float g_vs[8 * 32 * 32 * 512];        // [n][h][w][t1*64+z]

// ---------------------------------------------------------------------------
// 1) x -> g_xt  (NCHW -> padded NHWC, tf32 rounding)
// ---------------------------------------------------------------------------
__global__ __launch_bounds__(256) void xt_kernel(const float* __restrict__ x) {
    __shared__ float s[64 * 33];
    const int b = blockIdx.y, h0 = blockIdx.x;
    const int t = threadIdx.x;
    const int lane = t & 31, icg = t >> 5;
    const float* xp = x + ((size_t)(b * 32) * 64 + h0) * 64;
#pragma unroll
    for (int i = 0; i < 4; i++) {
        int ic = icg + 8 * i;
        s[lane * 33 + ic]        = xp[(size_t)ic * 4096 + lane];
        s[(lane + 32) * 33 + ic] = xp[(size_t)ic * 4096 + lane + 32];
    }
    __syncthreads();
    uint32_t* dst = (uint32_t*)(g_xt + (((size_t)b * 66 + h0 + 1) * 66 + 1) * 32);
#pragma unroll
    for (int i = 0; i < 8; i++) {
        int idx = t + 256 * i;
        int w0 = idx >> 5, ic = idx & 31;
        uint32_t u;
        asm("cvt.rna.tf32.f32 %0, %1;" : "=r"(u) : "f"(s[w0 * 33 + ic]));
        dst[idx] = u;
    }
}

// ---------------------------------------------------------------------------
// 2) W -> g_w2 [kpos][oc][ic] tf32
// ---------------------------------------------------------------------------
__global__ void w2_kernel(const float* __restrict__ W) {
    int idx = blockIdx.x * 256 + threadIdx.x;   // oc*288 + ic*9 + kp
    if (idx >= 512 * 288) return;
    int oc = idx / 288, r = idx % 288, ic = r / 9, kp = r % 9;
    uint32_t u;
    asm("cvt.rna.tf32.f32 %0, %1;" : "=r"(u) : "f"(W[idx]));
    ((uint32_t*)g_w2)[((size_t)kp * 512 + oc) * 32 + ic] = u;
}

// ---------------------------------------------------------------------------
// 3) conv via mma.sync tf32: D[oc=128][px=128] = sum_{9 kpos, 32 ic} W·X
//    grid (ptile=8, m=4, b=64), 256 threads, 2 CTAs/SM, double-buffered.
//    (R3 configuration — known-good compile/run at 262us total.)
// ---------------------------------------------------------------------------
#define TSTRIDE 36
#define TILE_F  (128 * TSTRIDE)   // floats per tile (A or B)

__global__ __launch_bounds__(256, 2) void conv_mma_kernel(const float* __restrict__ bias) {
    extern __shared__ float dsm[];
    const uint32_t sbase = smem_u32(dsm);
    const uint32_t offA[2] = {0u, 2u * TILE_F * 4u};
    const uint32_t offB[2] = {TILE_F * 4u, 3u * TILE_F * 4u};

    const int tid = threadIdx.x;
    const int wid = tid >> 5, lane = tid & 31;
    const int gid = lane >> 2, tig = lane & 3;

    const int pt = blockIdx.x;    // pixel tile (4 output rows)
    const int m  = blockIdx.y;    // oc block of 128
    const int b  = blockIdx.z;    // n*8 + t0
    const int h0 = pt * 4;

    const int m0 = (wid & 1) * 64;
    const int n0 = (wid >> 1) * 32;

    float acc[4][4][4];
#pragma unroll
    for (int mi = 0; mi < 4; mi++)
#pragma unroll
        for (int ni = 0; ni < 4; ni++)
#pragma unroll
            for (int j = 0; j < 4; j++) acc[mi][ni][j] = 0.f;

    auto issue = [&](int s, int buf) {
        const int kh = s / 3, kw = s % 3;
        const float4* Asrc = (const float4*)g_w2 + ((size_t)s * 512 + m * 128) * 8;
        const int ihb = 2 * h0 + kh;
#pragma unroll
        for (int i = 0; i < 4; i++) {
            int c = tid + 256 * i;
            int o = c >> 3, q = c & 7;
            cp16(sbase + offA[buf] + (o * TSTRIDE + q * 4) * 4, Asrc + c);
            int hl = o >> 5, wl = o & 31;
            const float4* src =
                (const float4*)g_xt + (((size_t)b * 66 + ihb + 2 * hl) * 66 + 2 * wl + kw) * 8 + q;
            cp16(sbase + offB[buf] + (o * TSTRIDE + q * 4) * 4, src);
        }
        asm volatile("cp.async.commit_group;");
    };

    issue(0, 0);

    for (int s = 0; s < 9; s++) {
        if (s < 8) {
            issue(s + 1, (s + 1) & 1);
            asm volatile("cp.async.wait_group 1;" ::: "memory");
        } else {
            asm volatile("cp.async.wait_group 0;" ::: "memory");
        }
        __syncthreads();

        const uint32_t* sA = (const uint32_t*)dsm + offA[s & 1] / 4;
        const uint32_t* sB = (const uint32_t*)dsm + offB[s & 1] / 4;

#pragma unroll
        for (int kk = 0; kk < 4; kk++) {
            const int kc = kk * 8 + tig;
            uint32_t a[4][4];
#pragma unroll
            for (int mi = 0; mi < 4; mi++) {
                int r = m0 + mi * 16 + gid;
                a[mi][0] = sA[r * TSTRIDE + kc];
                a[mi][1] = sA[(r + 8) * TSTRIDE + kc];
                a[mi][2] = sA[r * TSTRIDE + kc + 4];
                a[mi][3] = sA[(r + 8) * TSTRIDE + kc + 4];
            }
            uint32_t bf[4][2];
#pragma unroll
            for (int ni = 0; ni < 4; ni++) {
                int cn = n0 + ni * 8 + gid;
                bf[ni][0] = sB[cn * TSTRIDE + kc];
                bf[ni][1] = sB[cn * TSTRIDE + kc + 4];
            }
#pragma unroll
            for (int mi = 0; mi < 4; mi++)
#pragma unroll
                for (int ni = 0; ni < 4; ni++)
                    asm volatile(
                        "mma.sync.aligned.m16n8k8.row.col.f32.tf32.tf32.f32 "
                        "{%0,%1,%2,%3}, {%4,%5,%6,%7}, {%8,%9}, {%0,%1,%2,%3};"
                        : "+f"(acc[mi][ni][0]), "+f"(acc[mi][ni][1]),
                          "+f"(acc[mi][ni][2]), "+f"(acc[mi][ni][3])
                        : "r"(a[mi][0]), "r"(a[mi][1]), "r"(a[mi][2]), "r"(a[mi][3]),
                          "r"(bf[ni][0]), "r"(bf[ni][1]));
        }
        __syncthreads();
    }

    // Epilogue: regs -> stage[px][oc] (+bias) -> g_u2
    float* stage = dsm;
#pragma unroll
    for (int mi = 0; mi < 4; mi++) {
        int r = m0 + mi * 16 + gid;
        float bi0 = bias[m * 128 + r];
        float bi1 = bias[m * 128 + r + 8];
#pragma unroll
        for (int ni = 0; ni < 4; ni++) {
            int cn = n0 + ni * 8 + 2 * tig;
            stage[cn * 132 + r]           = acc[mi][ni][0] + bi0;
            stage[(cn + 1) * 132 + r]     = acc[mi][ni][1] + bi0;
            stage[cn * 132 + r + 8]       = acc[mi][ni][2] + bi1;
            stage[(cn + 1) * 132 + r + 8] = acc[mi][ni][3] + bi1;
        }
    }
    __syncthreads();

    const int n = b >> 3, t0 = b & 7;
#pragma unroll
    for (int k = 0; k < 16; k++) {
        int idx = tid + 256 * k;
        int p = idx >> 5, q = idx & 31;
        int h = h0 + (p >> 5), w = p & 31;
        float4 v = *(const float4*)(stage + p * 132 + q * 4);
        size_t off = ((((size_t)(n * 32 + h) * 32 + w) * 8 + t0) * 512) + m * 128 + q * 4;
        *(float4*)(g_u2 + off) = v;
    }
}

// ---------------------------------------------------------------------------
// 4) Routing iteration: u slice held in registers (R4 version, measured win).
// ---------------------------------------------------------------------------
template <int MODE>
__global__ __launch_bounds__(128) void route_kernel() {
    __shared__ float sr[64];

    const int pix = blockIdx.x;
    const int n = pix >> 10;
    const int hw = pix & 1023;
    const int tid = threadIdx.x;
    const int t1 = tid >> 4;
    const int z4 = tid & 15;

    if (MODE >= 1 && tid < 64) {
        int rt0 = tid >> 3, rt1 = tid & 7;
        sr[tid] = g_r[((n * 8 + rt0) * 1024 + hw) * 8 + rt1];
    }

    float4 u[8];
    const float4* up = (const float4*)g_u2 + (size_t)pix * 1024 + t1 * 16 + z4;
#pragma unroll
    for (int t0 = 0; t0 < 8; t0++) u[t0] = up[t0 * 128];

    if (MODE >= 1) __syncthreads();

    float4 p = make_float4(0.f, 0.f, 0.f, 0.f);
#pragma unroll
    for (int t0 = 0; t0 < 8; t0++) {
        float r = (MODE == 0) ? 0.125f : sr[t0 * 8 + t1];
        p.x += r * u[t0].x; p.y += r * u[t0].y; p.z += r * u[t0].z; p.w += r * u[t0].w;
    }
    float n2 = p.x * p.x + p.y * p.y + p.z * p.z + p.w * p.w;
#pragma unroll
    for (int mm = 1; mm < 16; mm <<= 1) n2 += __shfl_xor_sync(0xffffffffu, n2, mm);
    float s = n2 / (1.f + n2) * rsqrtf(n2 + 1e-9f);
    float4 v = make_float4(p.x * s, p.y * s, p.z * s, p.w * s);

    if (MODE == 2) {
        ((float4*)(g_vs + (size_t)pix * 512))[tid] = v;
    } else {
        float d[8];
#pragma unroll
        for (int t0 = 0; t0 < 8; t0++)
            d[t0] = u[t0].x * v.x + u[t0].y * v.y + u[t0].z * v.z + u[t0].w * v.w;
#pragma unroll
        for (int mm = 1; mm < 16; mm <<= 1) {
#pragma unroll
            for (int t0 = 0; t0 < 8; t0++)
                d[t0] += __shfl_xor_sync(0xffffffffu, d[t0], mm);
        }
        if ((tid & 15) == 0) {
#pragma unroll
            for (int t0 = 0; t0 < 8; t0++) {
                float* bp = &g_b[((n * 8 + t0) * 1024 + hw) * 8 + t1];
                if (MODE == 0) *bp = d[t0];
                else           *bp += d[t0];
            }
        }
    }
}

// ---------------------------------------------------------------------------
// 5) r = softmax_t1(maxpool3x3(b)).  grid (band=4, nt=64), 256 thr, h-banded.
// ---------------------------------------------------------------------------
__global__ __launch_bounds__(256) void pool_softmax_kernel() {
    __shared__ float sb[10 * 32 * 8];
    const int band = blockIdx.x, nt = blockIdx.y;
    const int tid = threadIdx.x;
    const int h_base = band * 8 - 1;

    for (int i = tid; i < 640; i += 256) {
        int lr = i >> 6, rem = i & 63;
        int gh = h_base + lr;
        float4 v;
        if (gh >= 0 && gh < 32)
            v = ((const float4*)(g_b + nt * 8192 + gh * 256))[rem];
        else
            v = make_float4(-3.4e38f, -3.4e38f, -3.4e38f, -3.4e38f);
        ((float4*)sb)[i] = v;
    }
    __syncthreads();

    const int hl = tid >> 5, w = tid & 31;
    float m[8];
#pragma unroll
    for (int t = 0; t < 8; t++) m[t] = -3.4e38f;
#pragma unroll
    for (int dh = 0; dh < 3; dh++) {
        int lr = hl + dh;
#pragma unroll
        for (int dw = -1; dw <= 1; dw++) {
            int ww = w + dw;
            if (ww < 0 || ww > 31) continue;
            const float* pp = &sb[(lr * 32 + ww) * 8];
#pragma unroll
            for (int t = 0; t < 8; t++) m[t] = fmaxf(m[t], pp[t]);
        }
    }
    float mx = m[0];
#pragma unroll
    for (int t = 1; t < 8; t++) mx = fmaxf(mx, m[t]);
    float e[8], ssum = 0.f;
#pragma unroll
    for (int t = 0; t < 8; t++) { e[t] = expf(m[t] - mx); ssum += e[t]; }
    float inv = 1.f / ssum;
    float* dst = &g_r[nt * 8192 + ((band * 8 + hl) * 32 + w) * 8];
    *(float4*)(dst + 0) = make_float4(e[0] * inv, e[1] * inv, e[2] * inv, e[3] * inv);
    *(float4*)(dst + 4) = make_float4(e[4] * inv, e[5] * inv, e[6] * inv, e[7] * inv);
}

// ---------------------------------------------------------------------------
// 6) transpose g_vs [n][hw][tz] -> out [n][tz][hw]
// ---------------------------------------------------------------------------
__global__ __launch_bounds__(256) void transpose_kernel(float* __restrict__ out) {
    __shared__ float t[32][33];
    const int n = blockIdx.z;
    const int x0 = blockIdx.x * 32;
    const int y0 = blockIdx.y * 32;
    const int tx = threadIdx.x & 31;
    const int ty = threadIdx.x >> 5;
    const float* src = g_vs + (size_t)n * 1024 * 512;
    float* dst = out + (size_t)n * 512 * 1024;
#pragma unroll
    for (int i = 0; i < 4; i++) {
        int y = ty + i * 8;
        t[y][tx] = src[(y0 + y) * 512 + x0 + tx];
    }
    __syncthreads();
#pragma unroll
    for (int i = 0; i < 4; i++) {
        int y = ty + i * 8;
        dst[(x0 + y) * 1024 + y0 + tx] = t[tx][y];
    }
}

// ---------------------------------------------------------------------------
extern "C" void kernel_launch(void* const* d_in, const int* in_sizes, int n_in,
                              void* d_out, int out_size) {
    const float* x    = (const float*)d_in[0];
    const float* W    = (const float*)d_in[1];
    const float* bias = (const float*)d_in[2];
    float* out = (float*)d_out;

    cudaFuncSetAttribute(conv_mma_kernel,
                         cudaFuncAttributeMaxDynamicSharedMemorySize, 4 * TILE_F * 4);

    xt_kernel<<<dim3(64, 64), 256>>>(x);
    w2_kernel<<<576, 256>>>(W);
    conv_mma_kernel<<<dim3(8, 4, 64), 256, 4 * TILE_F * 4>>>(bias);

    route_kernel<0><<<8192, 128>>>();
    pool_softmax_kernel<<<dim3(4, 64), 256>>>();
    route_kernel<1><<<8192, 128>>>();
    pool_softmax_kernel<<<dim3(4, 64), 256>>>();
    route_kernel<2><<<8192, 128>>>();

    dim3 tg(16, 32, 8);
    transpose_kernel<<<tg, 256>>>(out);
}